// round 1
// baseline (speedup 1.0000x reference)
#include <cuda_runtime.h>
#include <math.h>

#define BATCH 2
#define LSEQ  2048
#define VOCAB 32000
#define EDIM  512
#define HDIM  1024
#define MDIM  256
#define PDIM  4096
#define ROWS  (BATCH*LSEQ)   /* 4096 */
#define GRU_BLOCKS 128

// ---------------- scratch (__device__ globals: allocation-free) ----------------
__device__ float g_x[ROWS*EDIM];          // gathered embeddings  [4096,512]
__device__ float g_xp[(size_t)ROWS*3*HDIM];       // GRU input proj [4096,3072]
__device__ float g_states[(size_t)ROWS*HDIM];     // GRU states     [4096,1024]
__device__ float g_head[(size_t)ROWS*4*EDIM];     // relu^2 head    [4096,2048]
__device__ float g_feat[ROWS*EDIM];       // base_feat            [4096,512]
__device__ float g_q[ROWS*MDIM];
__device__ float g_k[ROWS*MDIM];
__device__ float g_gate[ROWS];            // sigmoid(gate)*memory_scale
__device__ float g_plin[(size_t)ROWS*PDIM];       // base_feat @ w_partial^T + b
__device__ float g_h[BATCH*HDIM];         // GRU hidden state (live)
__device__ int   g_t2p[VOCAB];
__device__ int   g_slots[ROWS];
__device__ unsigned g_bar;                // GRU grid barrier (monotonic)

// ---------------- init kernels ----------------
__global__ void init_a_kernel() {
    int i = blockIdx.x*256 + threadIdx.x;
    if (i < VOCAB) g_t2p[i] = -1;
    if (i < BATCH*HDIM) g_h[i] = 0.f;
    if (i == 0) g_bar = 0u;
}
__global__ void init_b_kernel(const int* __restrict__ untied) {
    int i = blockIdx.x*256 + threadIdx.x;
    if (i < PDIM) g_t2p[untied[i]] = i;
}
__global__ void init_c_kernel(const int* __restrict__ ids) {
    int i = blockIdx.x*256 + threadIdx.x;
    if (i < ROWS) g_slots[i] = g_t2p[ids[i]];
}
__global__ void gather_x_kernel(const int* __restrict__ ids, const float* __restrict__ emb) {
    int r = blockIdx.x;
    int tok = ids[r];
    const float4* src = reinterpret_cast<const float4*>(emb + (size_t)tok*EDIM);
    float4* dst = reinterpret_cast<float4*>(g_x + (size_t)r*EDIM);
    for (int i = threadIdx.x; i < EDIM/4; i += 128) dst[i] = src[i];
}

// ---------------- generic SGEMM: C[M,N] = A[M,K] * B[N,K]^T + bias (+epilogue) ----------------
// EPI: 0 = bias only, 1 = square(relu(x + bias))
template<int EPI>
__global__ __launch_bounds__(256) void sgemm_tn(
    const float* __restrict__ A, const float* __restrict__ B,
    const float* __restrict__ bias, float* __restrict__ C,
    int M, int N, int K)
{
    constexpr int BK = 16;
    __shared__ float As[BK][128];
    __shared__ float Bs[BK][128];
    const int bm = blockIdx.y * 128, bn = blockIdx.x * 128;
    const int tid = threadIdx.x;
    const int tx = tid & 15, ty = tid >> 4;
    float acc[8][8];
    #pragma unroll
    for (int i = 0; i < 8; i++)
        #pragma unroll
        for (int j = 0; j < 8; j++) acc[i][j] = 0.f;

    const float* Ab = A + (size_t)bm * K;
    const float* Bb = B + (size_t)bn * K;
    for (int k0 = 0; k0 < K; k0 += BK) {
        #pragma unroll
        for (int it = 0; it < 2; it++) {
            int idx = tid + it*256;         // 0..511
            int row = idx >> 2;
            int kc  = (idx & 3) << 2;
            float4 va = *reinterpret_cast<const float4*>(Ab + (size_t)row*K + k0 + kc);
            As[kc+0][row] = va.x; As[kc+1][row] = va.y; As[kc+2][row] = va.z; As[kc+3][row] = va.w;
            float4 vb = *reinterpret_cast<const float4*>(Bb + (size_t)row*K + k0 + kc);
            Bs[kc+0][row] = vb.x; Bs[kc+1][row] = vb.y; Bs[kc+2][row] = vb.z; Bs[kc+3][row] = vb.w;
        }
        __syncthreads();
        #pragma unroll
        for (int kk = 0; kk < BK; kk++) {
            float a[8], b[8];
            *reinterpret_cast<float4*>(&a[0]) = *reinterpret_cast<const float4*>(&As[kk][ty*8]);
            *reinterpret_cast<float4*>(&a[4]) = *reinterpret_cast<const float4*>(&As[kk][ty*8+4]);
            *reinterpret_cast<float4*>(&b[0]) = *reinterpret_cast<const float4*>(&Bs[kk][tx*8]);
            *reinterpret_cast<float4*>(&b[4]) = *reinterpret_cast<const float4*>(&Bs[kk][tx*8+4]);
            #pragma unroll
            for (int i = 0; i < 8; i++)
                #pragma unroll
                for (int j = 0; j < 8; j++)
                    acc[i][j] += a[i]*b[j];
        }
        __syncthreads();
    }
    #pragma unroll
    for (int i = 0; i < 8; i++) {
        size_t row = (size_t)(bm + ty*8 + i);
        float* crow = C + row*(size_t)N + bn + tx*8;
        #pragma unroll
        for (int j4 = 0; j4 < 8; j4 += 4) {
            float4 o;
            float* op = &o.x;
            #pragma unroll
            for (int j = 0; j < 4; j++) {
                float v = acc[i][j4+j] + bias[bn + tx*8 + j4 + j];
                if (EPI == 1) { v = v > 0.f ? v : 0.f; v = v*v; }
                op[j] = v;
            }
            *reinterpret_cast<float4*>(crow + j4) = o;
        }
    }
}

// ---------------- persistent GRU scan ----------------
// 128 blocks x 256 threads; block g owns h indices [8g, 8g+8); warp w owns index 8g+w.
// Each warp's lanes keep W_hh rows (r,z,n) for its index in registers (96 regs/thread).
__global__ __launch_bounds__(256, 1) void gru_kernel(
    const float* __restrict__ xp, const float* __restrict__ w_hh,
    const float* __restrict__ b_hh, float* __restrict__ states)
{
    const int warp = threadIdx.x >> 5;
    const int lane = threadIdx.x & 31;
    const int j = blockIdx.x * 8 + warp;

    float Wr[32], Wz[32], Wn[32];
    #pragma unroll
    for (int i = 0; i < 32; i++) {
        int c = lane + 32*i;
        Wr[i] = w_hh[(size_t)j*HDIM + c];
        Wz[i] = w_hh[(size_t)(HDIM + j)*HDIM + c];
        Wn[i] = w_hh[(size_t)(2*HDIM + j)*HDIM + c];
    }
    const float bhr = b_hh[j], bhz = b_hh[HDIM + j], bhn = b_hh[2*HDIM + j];

    __shared__ float hs[BATCH][HDIM];

    for (int t = 0; t < LSEQ; t++) {
        // pull current h (written by all blocks) through L2
        for (int idx = threadIdx.x; idx < BATCH*HDIM; idx += 256)
            (&hs[0][0])[idx] = __ldcg(&g_h[idx]);
        __syncthreads();

        float ar0=0.f,az0=0.f,an0=0.f, ar1=0.f,az1=0.f,an1=0.f;
        #pragma unroll
        for (int i = 0; i < 32; i++) {
            int c = lane + 32*i;
            float h0 = hs[0][c], h1 = hs[1][c];
            ar0 += Wr[i]*h0; az0 += Wz[i]*h0; an0 += Wn[i]*h0;
            ar1 += Wr[i]*h1; az1 += Wz[i]*h1; an1 += Wn[i]*h1;
        }
        #pragma unroll
        for (int off = 16; off; off >>= 1) {
            ar0 += __shfl_xor_sync(0xffffffffu, ar0, off);
            az0 += __shfl_xor_sync(0xffffffffu, az0, off);
            an0 += __shfl_xor_sync(0xffffffffu, an0, off);
            ar1 += __shfl_xor_sync(0xffffffffu, ar1, off);
            az1 += __shfl_xor_sync(0xffffffffu, az1, off);
            an1 += __shfl_xor_sync(0xffffffffu, an1, off);
        }
        if (lane < BATCH) {
            float hr, hz, hn;
            if (lane == 0) { hr = ar0; hz = az0; hn = an0; }
            else           { hr = ar1; hz = az1; hn = an1; }
            hr += bhr; hz += bhz; hn += bhn;
            const float* xrow = xp + ((size_t)(lane*LSEQ + t))*(3*HDIM);
            float r = 1.f/(1.f + __expf(-(xrow[j]          + hr)));
            float z = 1.f/(1.f + __expf(-(xrow[HDIM + j]   + hz)));
            float n = tanhf(xrow[2*HDIM + j] + r*hn);
            float hprev = hs[lane][j];
            float hnew = (1.f - z)*n + z*hprev;
            g_h[lane*HDIM + j] = hnew;
            states[((size_t)(lane*LSEQ + t))*HDIM + j] = hnew;
            __threadfence();
        }
        __syncthreads();
        if (threadIdx.x == 0) {
            atomicAdd(&g_bar, 1u);
            unsigned target = (unsigned)GRU_BLOCKS * (unsigned)(t + 1);
            while (*((volatile unsigned*)&g_bar) < target) { }
            __threadfence();
        }
        __syncthreads();
    }
}

// ---------------- gate ----------------
__global__ __launch_bounds__(256) void gate_kernel(
    const float* __restrict__ states, const float* __restrict__ wg,
    const float* __restrict__ bg, const float* __restrict__ ms)
{
    int r = blockIdx.x;
    float s = 0.f;
    for (int m = threadIdx.x; m < HDIM; m += 256)
        s += states[(size_t)r*HDIM + m] * wg[m];
    __shared__ float red[256];
    red[threadIdx.x] = s; __syncthreads();
    for (int o = 128; o; o >>= 1) { if (threadIdx.x < o) red[threadIdx.x] += red[threadIdx.x + o]; __syncthreads(); }
    if (threadIdx.x == 0) {
        float v = red[0] + bg[0];
        g_gate[r] = (1.f/(1.f + __expf(-v))) * ms[0];
    }
}

// ---------------- attention + softmax + scatter + final untied add ----------------
__global__ __launch_bounds__(256) void attn_scatter_kernel(
    const int* __restrict__ untied, float* __restrict__ out)
{
    const int r = blockIdx.x;
    const int b = r >> 11, l = r & (LSEQ - 1);
    const int tid = threadIdx.x;
    __shared__ float q_s[MDIM];
    __shared__ float sc[LSEQ];
    __shared__ float accp[PDIM];
    __shared__ float red[256];

    for (int p = tid; p < PDIM; p += 256) accp[p] = 0.f;

    if (l > 0) {
        for (int m = tid; m < MDIM; m += 256) q_s[m] = g_q[(size_t)r*MDIM + m];
        __syncthreads();
        const float* kb = g_k + (size_t)b*LSEQ*MDIM;
        for (int jj = tid; jj < l; jj += 256) {
            const float4* kr = reinterpret_cast<const float4*>(kb + (size_t)jj*MDIM);
            const float4* qr = reinterpret_cast<const float4*>(q_s);
            float s = 0.f;
            #pragma unroll 8
            for (int m = 0; m < MDIM/4; m++) {
                float4 kv = kr[m], qv = qr[m];
                s += kv.x*qv.x + kv.y*qv.y + kv.z*qv.z + kv.w*qv.w;
            }
            sc[jj] = s * 0.0625f;   // 1/sqrt(256)
        }
        __syncthreads();
        float mx = -3.4e38f;
        for (int jj = tid; jj < l; jj += 256) mx = fmaxf(mx, sc[jj]);
        red[tid] = mx; __syncthreads();
        for (int o = 128; o; o >>= 1) { if (tid < o) red[tid] = fmaxf(red[tid], red[tid + o]); __syncthreads(); }
        mx = red[0]; __syncthreads();
        float ls = 0.f;
        for (int jj = tid; jj < l; jj += 256) { float e = __expf(sc[jj] - mx); sc[jj] = e; ls += e; }
        red[tid] = ls; __syncthreads();
        for (int o = 128; o; o >>= 1) { if (tid < o) red[tid] += red[tid + o]; __syncthreads(); }
        float coef = g_gate[r] / red[0];
        const int* sl = g_slots + b*LSEQ;
        for (int jj = tid; jj < l; jj += 256) {
            int s = sl[jj];
            if (s >= 0) atomicAdd(&accp[s], sc[jj]*coef);
        }
    }
    __syncthreads();
    const float* pl = g_plin + (size_t)r*PDIM;
    float* orow = out + (size_t)r*VOCAB;
    for (int p = tid; p < PDIM; p += 256) {
        int col = untied[p];
        orow[col] += accp[p] + pl[p];
    }
}

// ---------------- launch ----------------
extern "C" void kernel_launch(void* const* d_in, const int* in_sizes, int n_in,
                              void* d_out, int out_size)
{
    const int*   ids     = (const int*)  d_in[0];
    const int*   untied  = (const int*)  d_in[1];
    const float* emb     = (const float*)d_in[2];
    const float* w_ih    = (const float*)d_in[3];
    const float* w_hh    = (const float*)d_in[4];
    const float* b_ih    = (const float*)d_in[5];
    const float* b_hh    = (const float*)d_in[6];
    const float* wq      = (const float*)d_in[7];
    const float* bq      = (const float*)d_in[8];
    const float* wk      = (const float*)d_in[9];
    const float* bk      = (const float*)d_in[10];
    const float* wg      = (const float*)d_in[11];
    const float* bg      = (const float*)d_in[12];
    const float* w_fc    = (const float*)d_in[13];
    const float* b_fc    = (const float*)d_in[14];
    const float* w_proj  = (const float*)d_in[15];
    const float* b_proj  = (const float*)d_in[16];
    const float* obias   = (const float*)d_in[17];
    const float* w_part  = (const float*)d_in[18];
    const float* b_part  = (const float*)d_in[19];
    const float* mscale  = (const float*)d_in[20];
    float* out = (float*)d_out;

    float *px, *pxp, *pstates, *phead, *pfeat, *pq, *pk, *pplin;
    cudaGetSymbolAddress((void**)&px,      g_x);
    cudaGetSymbolAddress((void**)&pxp,     g_xp);
    cudaGetSymbolAddress((void**)&pstates, g_states);
    cudaGetSymbolAddress((void**)&phead,   g_head);
    cudaGetSymbolAddress((void**)&pfeat,   g_feat);
    cudaGetSymbolAddress((void**)&pq,      g_q);
    cudaGetSymbolAddress((void**)&pk,      g_k);
    cudaGetSymbolAddress((void**)&pplin,   g_plin);

    init_a_kernel<<<(VOCAB + 255)/256, 256>>>();
    init_b_kernel<<<(PDIM + 255)/256, 256>>>(untied);
    init_c_kernel<<<(ROWS + 255)/256, 256>>>(ids);
    gather_x_kernel<<<ROWS, 128>>>(ids, emb);

    // xp = x @ w_ih^T + b_ih        [4096, 3072]
    sgemm_tn<0><<<dim3(3*HDIM/128, ROWS/128), 256>>>(px, w_ih, b_ih, pxp, ROWS, 3*HDIM, EDIM);

    // sequential GRU scan -> states [4096, 1024]
    gru_kernel<<<GRU_BLOCKS, 256>>>(pxp, w_hh, b_hh, pstates);

    // head = relu(states @ w_fc^T + b_fc)^2   [4096, 2048]
    sgemm_tn<1><<<dim3(4*EDIM/128, ROWS/128), 256>>>(pstates, w_fc, b_fc, phead, ROWS, 4*EDIM, HDIM);
    // base_feat = head @ w_proj^T + b_proj    [4096, 512]
    sgemm_tn<0><<<dim3(EDIM/128, ROWS/128), 256>>>(phead, w_proj, b_proj, pfeat, ROWS, EDIM, 4*EDIM);
    // q / k                                   [4096, 256]
    sgemm_tn<0><<<dim3(MDIM/128, ROWS/128), 256>>>(pstates, wq, bq, pq, ROWS, MDIM, HDIM);
    sgemm_tn<0><<<dim3(MDIM/128, ROWS/128), 256>>>(pstates, wk, bk, pk, ROWS, MDIM, HDIM);
    // gate (includes memory_scale)
    gate_kernel<<<ROWS, 256>>>(pstates, wg, bg, mscale);

    // base_logits = base_feat @ emb^T + output_bias  -> d_out  [4096, 32000]
    sgemm_tn<0><<<dim3(VOCAB/128, ROWS/128), 256>>>(pfeat, emb, obias, out, ROWS, VOCAB, EDIM);
    // part_lin = base_feat @ w_partial^T + b_partial [4096, 4096]
    sgemm_tn<0><<<dim3(PDIM/128, ROWS/128), 256>>>(pfeat, w_part, b_part, pplin, ROWS, PDIM, EDIM);

    // attention softmax + gated scatter + untied column add into d_out
    attn_scatter_kernel<<<ROWS, 256>>>(untied, out);
}

// round 2
// speedup vs baseline: 1.0657x; 1.0657x over previous
#include <cuda_runtime.h>
#include <mma.h>
#include <math.h>

using namespace nvcuda;

#define BATCH 2
#define LSEQ  2048
#define VOCAB 32000
#define EDIM  512
#define HDIM  1024
#define MDIM  256
#define PDIM  4096
#define ROWS  (BATCH*LSEQ)   /* 4096 */
#define GRU_BLOCKS 128

// ---------------- scratch (__device__ globals: allocation-free) ----------------
__device__ float g_x[ROWS*EDIM];
__device__ float g_xp[(size_t)ROWS*3*HDIM];
__device__ float g_states[(size_t)ROWS*HDIM];
__device__ float g_head[(size_t)ROWS*4*EDIM];
__device__ float g_feat[ROWS*EDIM];
__device__ float g_q[ROWS*MDIM];
__device__ float g_k[ROWS*MDIM];
__device__ float g_gate[ROWS];
__device__ float g_plin[(size_t)ROWS*PDIM];
__device__ float g_h[BATCH*HDIM];
__device__ int   g_t2p[VOCAB];
__device__ int   g_slots[ROWS];
__device__ unsigned g_bar;

// ---------------- init kernels ----------------
__global__ void init_a_kernel() {
    int i = blockIdx.x*256 + threadIdx.x;
    if (i < VOCAB) g_t2p[i] = -1;
    if (i < BATCH*HDIM) g_h[i] = 0.f;
    if (i == 0) g_bar = 0u;
}
__global__ void init_b_kernel(const int* __restrict__ untied) {
    int i = blockIdx.x*256 + threadIdx.x;
    if (i < PDIM) g_t2p[untied[i]] = i;
}
__global__ void init_c_kernel(const int* __restrict__ ids) {
    int i = blockIdx.x*256 + threadIdx.x;
    if (i < ROWS) g_slots[i] = g_t2p[ids[i]];
}
__global__ void gather_x_kernel(const int* __restrict__ ids, const float* __restrict__ emb) {
    int r = blockIdx.x;
    int tok = ids[r];
    const float4* src = reinterpret_cast<const float4*>(emb + (size_t)tok*EDIM);
    float4* dst = reinterpret_cast<float4*>(g_x + (size_t)r*EDIM);
    for (int i = threadIdx.x; i < EDIM/4; i += 128) dst[i] = src[i];
}

// ---------------- TF32 tensor-core GEMM: C[M,N] = A[M,K] * B[N,K]^T + bias ----------------
// EPI: 0 = bias only, 1 = square(relu(x + bias))
// Tiles: 128x128x32, 8 warps, warp tile 32x64 (2x4 wmma m16n16k8 frags).
#define BK32 32
#define LDS_AB 40   /* 32 + 8 pad; 160B row stride -> 16B aligned rows */

struct SmemU {
    union {
        struct { float As[128][LDS_AB]; float Bs[128][LDS_AB]; } ab;
        float patch[8][16][24];
    };
};

template<int EPI>
__global__ __launch_bounds__(256, 2) void wgemm_tn(
    const float* __restrict__ A, const float* __restrict__ B,
    const float* __restrict__ bias, float* __restrict__ C,
    int M, int N, int K)
{
    __shared__ __align__(16) SmemU sm;

    const int tid  = threadIdx.x;
    const int warp = tid >> 5;
    const int lane = tid & 31;
    const int wm   = warp & 3;          // 0..3 -> 32-row stripes
    const int wn   = warp >> 2;         // 0..1 -> 64-col stripes
    const int bm   = blockIdx.y * 128, bn = blockIdx.x * 128;

    wmma::fragment<wmma::accumulator,16,16,8,float> acc[2][4];
    #pragma unroll
    for (int im = 0; im < 2; im++)
        #pragma unroll
        for (int in = 0; in < 4; in++) wmma::fill_fragment(acc[im][in], 0.f);

    const float* Ab = A + (size_t)bm * K;
    const float* Bb = B + (size_t)bn * K;

    float4 ra[4], rb[4];
    // each thread: 4 float4 per matrix per K-tile (128 rows x 8 float4)
    #pragma unroll
    for (int i = 0; i < 4; i++) {
        int idx = tid + i*256;
        int row = idx >> 3, c4 = (idx & 7) << 2;
        ra[i] = *reinterpret_cast<const float4*>(Ab + (size_t)row*K + c4);
        rb[i] = *reinterpret_cast<const float4*>(Bb + (size_t)row*K + c4);
    }
    #pragma unroll
    for (int i = 0; i < 4; i++) {
        int idx = tid + i*256;
        int row = idx >> 3, c4 = (idx & 7) << 2;
        *reinterpret_cast<float4*>(&sm.ab.As[row][c4]) = ra[i];
        *reinterpret_cast<float4*>(&sm.ab.Bs[row][c4]) = rb[i];
    }
    __syncthreads();

    for (int k0 = 0; k0 < K; k0 += BK32) {
        const bool more = (k0 + BK32 < K);
        if (more) {
            #pragma unroll
            for (int i = 0; i < 4; i++) {
                int idx = tid + i*256;
                int row = idx >> 3, c4 = (idx & 7) << 2;
                ra[i] = *reinterpret_cast<const float4*>(Ab + (size_t)row*K + k0 + BK32 + c4);
                rb[i] = *reinterpret_cast<const float4*>(Bb + (size_t)row*K + k0 + BK32 + c4);
            }
        }
        #pragma unroll
        for (int kk = 0; kk < BK32; kk += 8) {
            wmma::fragment<wmma::matrix_a,16,16,8,wmma::precision::tf32,wmma::row_major> af[2];
            wmma::fragment<wmma::matrix_b,16,16,8,wmma::precision::tf32,wmma::col_major> bf[4];
            #pragma unroll
            for (int im = 0; im < 2; im++) {
                wmma::load_matrix_sync(af[im], &sm.ab.As[wm*32 + im*16][kk], LDS_AB);
                #pragma unroll
                for (int e = 0; e < af[im].num_elements; e++)
                    af[im].x[e] = wmma::__float_to_tf32(af[im].x[e]);
            }
            #pragma unroll
            for (int in = 0; in < 4; in++) {
                wmma::load_matrix_sync(bf[in], &sm.ab.Bs[wn*64 + in*16][kk], LDS_AB);
                #pragma unroll
                for (int e = 0; e < bf[in].num_elements; e++)
                    bf[in].x[e] = wmma::__float_to_tf32(bf[in].x[e]);
            }
            #pragma unroll
            for (int im = 0; im < 2; im++)
                #pragma unroll
                for (int in = 0; in < 4; in++)
                    wmma::mma_sync(acc[im][in], af[im], bf[in], acc[im][in]);
        }
        __syncthreads();
        if (more) {
            #pragma unroll
            for (int i = 0; i < 4; i++) {
                int idx = tid + i*256;
                int row = idx >> 3, c4 = (idx & 7) << 2;
                *reinterpret_cast<float4*>(&sm.ab.As[row][c4]) = ra[i];
                *reinterpret_cast<float4*>(&sm.ab.Bs[row][c4]) = rb[i];
            }
            __syncthreads();
        }
    }

    // epilogue: stage each 16x16 frag through per-warp smem patch
    #pragma unroll
    for (int im = 0; im < 2; im++)
        #pragma unroll
        for (int in = 0; in < 4; in++) {
            wmma::store_matrix_sync(&sm.patch[warp][0][0], acc[im][in], 24, wmma::mem_row_major);
            __syncwarp();
            const int row0 = bm + wm*32 + im*16;
            const int col0 = bn + wn*64 + in*16;
            #pragma unroll
            for (int e = 0; e < 8; e++) {
                int idx = lane*8 + e;        // 0..255
                int r = idx >> 4, c = idx & 15;
                float v = sm.patch[warp][r][c] + __ldg(&bias[col0 + c]);
                if (EPI == 1) { v = v > 0.f ? v : 0.f; v = v*v; }
                C[(size_t)(row0 + r)*N + col0 + c] = v;
            }
            __syncwarp();
        }
}

// ---------------- persistent GRU scan ----------------
__global__ __launch_bounds__(256, 1) void gru_kernel(
    const float* __restrict__ xp, const float* __restrict__ w_hh,
    const float* __restrict__ b_hh, float* __restrict__ states)
{
    const int warp = threadIdx.x >> 5;
    const int lane = threadIdx.x & 31;
    const int j = blockIdx.x * 8 + warp;

    float Wr[32], Wz[32], Wn[32];
    #pragma unroll
    for (int i = 0; i < 32; i++) {
        int c = lane + 32*i;
        Wr[i] = w_hh[(size_t)j*HDIM + c];
        Wz[i] = w_hh[(size_t)(HDIM + j)*HDIM + c];
        Wn[i] = w_hh[(size_t)(2*HDIM + j)*HDIM + c];
    }
    const float bhr = b_hh[j], bhz = b_hh[HDIM + j], bhn = b_hh[2*HDIM + j];

    __shared__ float hs[BATCH][HDIM];

    for (int t = 0; t < LSEQ; t++) {
        for (int idx = threadIdx.x; idx < BATCH*HDIM; idx += 256)
            (&hs[0][0])[idx] = __ldcg(&g_h[idx]);
        __syncthreads();

        float ar0=0.f,az0=0.f,an0=0.f, ar1=0.f,az1=0.f,an1=0.f;
        #pragma unroll
        for (int i = 0; i < 32; i++) {
            int c = lane + 32*i;
            float h0 = hs[0][c], h1 = hs[1][c];
            ar0 += Wr[i]*h0; az0 += Wz[i]*h0; an0 += Wn[i]*h0;
            ar1 += Wr[i]*h1; az1 += Wz[i]*h1; an1 += Wn[i]*h1;
        }
        #pragma unroll
        for (int off = 16; off; off >>= 1) {
            ar0 += __shfl_xor_sync(0xffffffffu, ar0, off);
            az0 += __shfl_xor_sync(0xffffffffu, az0, off);
            an0 += __shfl_xor_sync(0xffffffffu, an0, off);
            ar1 += __shfl_xor_sync(0xffffffffu, ar1, off);
            az1 += __shfl_xor_sync(0xffffffffu, az1, off);
            an1 += __shfl_xor_sync(0xffffffffu, an1, off);
        }
        if (lane < BATCH) {
            float hr, hz, hn;
            if (lane == 0) { hr = ar0; hz = az0; hn = an0; }
            else           { hr = ar1; hz = az1; hn = an1; }
            hr += bhr; hz += bhz; hn += bhn;
            const float* xrow = xp + ((size_t)(lane*LSEQ + t))*(3*HDIM);
            float r = 1.f/(1.f + __expf(-(xrow[j]          + hr)));
            float z = 1.f/(1.f + __expf(-(xrow[HDIM + j]   + hz)));
            float n = tanhf(xrow[2*HDIM + j] + r*hn);
            float hprev = hs[lane][j];
            float hnew = (1.f - z)*n + z*hprev;
            g_h[lane*HDIM + j] = hnew;
            states[((size_t)(lane*LSEQ + t))*HDIM + j] = hnew;
            __threadfence();
        }
        __syncthreads();
        if (threadIdx.x == 0) {
            atomicAdd(&g_bar, 1u);
            unsigned target = (unsigned)GRU_BLOCKS * (unsigned)(t + 1);
            while (*((volatile unsigned*)&g_bar) < target) { }
            __threadfence();
        }
        __syncthreads();
    }
}

// ---------------- gate ----------------
__global__ __launch_bounds__(256) void gate_kernel(
    const float* __restrict__ states, const float* __restrict__ wg,
    const float* __restrict__ bg, const float* __restrict__ ms)
{
    int r = blockIdx.x;
    float s = 0.f;
    for (int m = threadIdx.x; m < HDIM; m += 256)
        s += states[(size_t)r*HDIM + m] * wg[m];
    __shared__ float red[256];
    red[threadIdx.x] = s; __syncthreads();
    for (int o = 128; o; o >>= 1) { if (threadIdx.x < o) red[threadIdx.x] += red[threadIdx.x + o]; __syncthreads(); }
    if (threadIdx.x == 0) {
        float v = red[0] + bg[0];
        g_gate[r] = (1.f/(1.f + __expf(-v))) * ms[0];
    }
}

// ---------------- attention + softmax + scatter + final untied add ----------------
__global__ __launch_bounds__(256) void attn_scatter_kernel(
    const int* __restrict__ untied, float* __restrict__ out)
{
    const int r = blockIdx.x;
    const int b = r >> 11, l = r & (LSEQ - 1);
    const int tid = threadIdx.x;
    __shared__ float q_s[MDIM];
    __shared__ float sc[LSEQ];
    __shared__ float accp[PDIM];
    __shared__ float red[256];

    for (int p = tid; p < PDIM; p += 256) accp[p] = 0.f;

    if (l > 0) {
        for (int m = tid; m < MDIM; m += 256) q_s[m] = g_q[(size_t)r*MDIM + m];
        __syncthreads();
        const float* kb = g_k + (size_t)b*LSEQ*MDIM;
        for (int jj = tid; jj < l; jj += 256) {
            const float4* kr = reinterpret_cast<const float4*>(kb + (size_t)jj*MDIM);
            const float4* qr = reinterpret_cast<const float4*>(q_s);
            float s = 0.f;
            #pragma unroll 8
            for (int m = 0; m < MDIM/4; m++) {
                float4 kv = kr[m], qv = qr[m];
                s += kv.x*qv.x + kv.y*qv.y + kv.z*qv.z + kv.w*qv.w;
            }
            sc[jj] = s * 0.0625f;
        }
        __syncthreads();
        float mx = -3.4e38f;
        for (int jj = tid; jj < l; jj += 256) mx = fmaxf(mx, sc[jj]);
        red[tid] = mx; __syncthreads();
        for (int o = 128; o; o >>= 1) { if (tid < o) red[tid] = fmaxf(red[tid], red[tid + o]); __syncthreads(); }
        mx = red[0]; __syncthreads();
        float ls = 0.f;
        for (int jj = tid; jj < l; jj += 256) { float e = __expf(sc[jj] - mx); sc[jj] = e; ls += e; }
        red[tid] = ls; __syncthreads();
        for (int o = 128; o; o >>= 1) { if (tid < o) red[tid] += red[tid + o]; __syncthreads(); }
        float coef = g_gate[r] / red[0];
        const int* sl = g_slots + b*LSEQ;
        for (int jj = tid; jj < l; jj += 256) {
            int s = sl[jj];
            if (s >= 0) atomicAdd(&accp[s], sc[jj]*coef);
        }
    }
    __syncthreads();
    const float* pl = g_plin + (size_t)r*PDIM;
    float* orow = out + (size_t)r*VOCAB;
    for (int p = tid; p < PDIM; p += 256) {
        int col = untied[p];
        orow[col] += accp[p] + pl[p];
    }
}

// ---------------- launch ----------------
extern "C" void kernel_launch(void* const* d_in, const int* in_sizes, int n_in,
                              void* d_out, int out_size)
{
    const int*   ids     = (const int*)  d_in[0];
    const int*   untied  = (const int*)  d_in[1];
    const float* emb     = (const float*)d_in[2];
    const float* w_ih    = (const float*)d_in[3];
    const float* w_hh    = (const float*)d_in[4];
    const float* b_ih    = (const float*)d_in[5];
    const float* b_hh    = (const float*)d_in[6];
    const float* wq      = (const float*)d_in[7];
    const float* bq      = (const float*)d_in[8];
    const float* wk      = (const float*)d_in[9];
    const float* bk      = (const float*)d_in[10];
    const float* wg      = (const float*)d_in[11];
    const float* bg      = (const float*)d_in[12];
    const float* w_fc    = (const float*)d_in[13];
    const float* b_fc    = (const float*)d_in[14];
    const float* w_proj  = (const float*)d_in[15];
    const float* b_proj  = (const float*)d_in[16];
    const float* obias   = (const float*)d_in[17];
    const float* w_part  = (const float*)d_in[18];
    const float* b_part  = (const float*)d_in[19];
    const float* mscale  = (const float*)d_in[20];
    float* out = (float*)d_out;

    float *px, *pxp, *pstates, *phead, *pfeat, *pq, *pk, *pplin;
    cudaGetSymbolAddress((void**)&px,      g_x);
    cudaGetSymbolAddress((void**)&pxp,     g_xp);
    cudaGetSymbolAddress((void**)&pstates, g_states);
    cudaGetSymbolAddress((void**)&phead,   g_head);
    cudaGetSymbolAddress((void**)&pfeat,   g_feat);
    cudaGetSymbolAddress((void**)&pq,      g_q);
    cudaGetSymbolAddress((void**)&pk,      g_k);
    cudaGetSymbolAddress((void**)&pplin,   g_plin);

    init_a_kernel<<<(VOCAB + 255)/256, 256>>>();
    init_b_kernel<<<(PDIM + 255)/256, 256>>>(untied);
    init_c_kernel<<<(ROWS + 255)/256, 256>>>(ids);
    gather_x_kernel<<<ROWS, 128>>>(ids, emb);

    // xp = x @ w_ih^T + b_ih        [4096, 3072]
    wgemm_tn<0><<<dim3(3*HDIM/128, ROWS/128), 256>>>(px, w_ih, b_ih, pxp, ROWS, 3*HDIM, EDIM);

    // sequential GRU scan -> states [4096, 1024]
    gru_kernel<<<GRU_BLOCKS, 256>>>(pxp, w_hh, b_hh, pstates);

    // head = relu(states @ w_fc^T + b_fc)^2   [4096, 2048]
    wgemm_tn<1><<<dim3(4*EDIM/128, ROWS/128), 256>>>(pstates, w_fc, b_fc, phead, ROWS, 4*EDIM, HDIM);
    // base_feat = head @ w_proj^T + b_proj    [4096, 512]
    wgemm_tn<0><<<dim3(EDIM/128, ROWS/128), 256>>>(phead, w_proj, b_proj, pfeat, ROWS, EDIM, 4*EDIM);
    // q / k                                   [4096, 256]
    wgemm_tn<0><<<dim3(MDIM/128, ROWS/128), 256>>>(pstates, wq, bq, pq, ROWS, MDIM, HDIM);
    wgemm_tn<0><<<dim3(MDIM/128, ROWS/128), 256>>>(pstates, wk, bk, pk, ROWS, MDIM, HDIM);
    // gate (includes memory_scale)
    gate_kernel<<<ROWS, 256>>>(pstates, wg, bg, mscale);

    // base_logits = base_feat @ emb^T + output_bias  -> d_out  [4096, 32000]
    wgemm_tn<0><<<dim3(VOCAB/128, ROWS/128), 256>>>(pfeat, emb, obias, out, ROWS, VOCAB, EDIM);
    // part_lin = base_feat @ w_partial^T + b_partial [4096, 4096]
    wgemm_tn<0><<<dim3(PDIM/128, ROWS/128), 256>>>(pfeat, w_part, b_part, pplin, ROWS, PDIM, EDIM);

    // attention softmax + gated scatter + untied column add into d_out
    attn_scatter_kernel<<<ROWS, 256>>>(untied, out);
}

// round 4
// speedup vs baseline: 1.3331x; 1.2510x over previous
#include <cuda_runtime.h>
#include <cuda_bf16.h>
#include <mma.h>
#include <math.h>
#include <stdint.h>

using namespace nvcuda;

#define BATCH 2
#define LSEQ  2048
#define VOCAB 32000
#define EDIM  512
#define HDIM  1024
#define MDIM  256
#define PDIM  4096
#define ROWS  (BATCH*LSEQ)   /* 4096 */
#define GRU_BLOCKS 128

// ---------------- scratch (__device__ globals: allocation-free) ----------------
__device__ float g_xp[(size_t)ROWS*3*HDIM];
__device__ float g_states[(size_t)ROWS*HDIM];
__device__ float g_q[ROWS*MDIM];
__device__ float g_k[ROWS*MDIM];
__device__ float g_gate[ROWS];
__device__ float g_plin[(size_t)ROWS*PDIM];
__device__ float g_h[BATCH*HDIM];
__device__ int   g_t2p[VOCAB];
__device__ int   g_slots[ROWS];
__device__ unsigned g_bar;

// bf16 copies for tensor-core GEMMs
__device__ __nv_bfloat16 g_x_bf[ROWS*EDIM];
__device__ __nv_bfloat16 g_emb_bf[(size_t)VOCAB*EDIM];
__device__ __nv_bfloat16 g_states_bf[(size_t)ROWS*HDIM];
__device__ __nv_bfloat16 g_head_bf[(size_t)ROWS*4*EDIM];
__device__ __nv_bfloat16 g_feat_bf[ROWS*EDIM];
__device__ __nv_bfloat16 g_wih_bf[3*HDIM*EDIM];
__device__ __nv_bfloat16 g_wfc_bf[4*EDIM*HDIM];
__device__ __nv_bfloat16 g_wproj_bf[EDIM*4*EDIM];
__device__ __nv_bfloat16 g_wq_bf[MDIM*HDIM];
__device__ __nv_bfloat16 g_wk_bf[MDIM*HDIM];
__device__ __nv_bfloat16 g_wpart_bf[PDIM*EDIM];

// ---------------- init / convert kernels ----------------
__global__ void init_a_kernel() {
    int i = blockIdx.x*256 + threadIdx.x;
    if (i < VOCAB) g_t2p[i] = -1;
    if (i < BATCH*HDIM) g_h[i] = 0.f;
    if (i == 0) g_bar = 0u;
}
__global__ void init_b_kernel(const int* __restrict__ untied) {
    int i = blockIdx.x*256 + threadIdx.x;
    if (i < PDIM) g_t2p[untied[i]] = i;
}
__global__ void init_c_kernel(const int* __restrict__ ids) {
    int i = blockIdx.x*256 + threadIdx.x;
    if (i < ROWS) g_slots[i] = g_t2p[ids[i]];
}
__global__ void f2bf_kernel(const float* __restrict__ s, __nv_bfloat16* __restrict__ d, int n4) {
    int i = blockIdx.x*256 + threadIdx.x;
    if (i < n4) {
        float4 v = reinterpret_cast<const float4*>(s)[i];
        __nv_bfloat162 lo = __floats2bfloat162_rn(v.x, v.y);
        __nv_bfloat162 hi = __floats2bfloat162_rn(v.z, v.w);
        uint2 o;
        o.x = *reinterpret_cast<unsigned int*>(&lo);
        o.y = *reinterpret_cast<unsigned int*>(&hi);
        reinterpret_cast<uint2*>(d)[i] = o;
    }
}
__global__ void gather_x_bf_kernel(const int* __restrict__ ids, const float* __restrict__ emb) {
    int r = blockIdx.x;
    int tok = ids[r];
    const float4* src = reinterpret_cast<const float4*>(emb + (size_t)tok*EDIM);
    uint2* dst = reinterpret_cast<uint2*>(g_x_bf + (size_t)r*EDIM);
    for (int i = threadIdx.x; i < EDIM/4; i += 128) {
        float4 v = src[i];
        __nv_bfloat162 lo = __floats2bfloat162_rn(v.x, v.y);
        __nv_bfloat162 hi = __floats2bfloat162_rn(v.z, v.w);
        uint2 o;
        o.x = *reinterpret_cast<unsigned int*>(&lo);
        o.y = *reinterpret_cast<unsigned int*>(&hi);
        dst[i] = o;
    }
}

// ---------------- bf16 tensor-core GEMM: C[M,N] = A[M,K] * B[N,K]^T + bias ----------------
// EPI: 0 = bias only, 1 = square(relu(x+bias)).  OBF: 0 -> fp32 C, 1 -> bf16 Cb.
// Tiles 128x128x32, 8 warps (warp tile 32x64 = 2x4 m16n16k16 frags), 2-stage cp.async.
#define LDH 40   /* 40 bf16 = 80B row stride: 16B multiple, conflict-free ldmatrix */

struct SmemH {
    union {
        __nv_bfloat16 ab[2][2][128][LDH];   // [stage][A=0/B=1][row][k]  (40 KB)
        float patch[8][16][24];             // per-warp epilogue staging (12 KB)
    };
};

__device__ __forceinline__ void cp_async16(void* smem, const void* gmem) {
    unsigned int s = (unsigned int)__cvta_generic_to_shared(smem);
    asm volatile("cp.async.cg.shared.global [%0], [%1], 16;\n" :: "r"(s), "l"(gmem) : "memory");
}

template<int EPI, int OBF>
__global__ __launch_bounds__(256, 2) void hgemm_tn(
    const __nv_bfloat16* __restrict__ A, const __nv_bfloat16* __restrict__ B,
    const float* __restrict__ bias, float* __restrict__ C, __nv_bfloat16* __restrict__ Cb,
    int M, int N, int K)
{
    __shared__ __align__(16) SmemH sm;

    const int tid  = threadIdx.x;
    const int warp = tid >> 5;
    const int lane = tid & 31;
    const int wm   = warp & 3;
    const int wn   = warp >> 2;
    const int bm   = blockIdx.y * 128, bn = blockIdx.x * 128;

    const __nv_bfloat16* Ab = A + (size_t)bm * K;
    const __nv_bfloat16* Bb = B + (size_t)bn * K;

    wmma::fragment<wmma::accumulator,16,16,16,float> acc[2][4];
    #pragma unroll
    for (int im = 0; im < 2; im++)
        #pragma unroll
        for (int in = 0; in < 4; in++) wmma::fill_fragment(acc[im][in], 0.f);

    auto load_tile = [&](int st, int k0) {
        #pragma unroll
        for (int i = 0; i < 2; i++) {
            int idx = tid + i*256;            // 0..511
            int row = idx >> 2, ch = (idx & 3) << 3;
            cp_async16(&sm.ab[st][0][row][ch], Ab + (size_t)row*K + k0 + ch);
            cp_async16(&sm.ab[st][1][row][ch], Bb + (size_t)row*K + k0 + ch);
        }
        asm volatile("cp.async.commit_group;\n" ::: "memory");
    };

    const int T = K >> 5;
    load_tile(0, 0);
    for (int t = 0; t < T; t++) {
        const int st = t & 1;
        asm volatile("cp.async.wait_group 0;\n" ::: "memory");
        __syncthreads();
        if (t + 1 < T) load_tile((t + 1) & 1, (t + 1) << 5);
        #pragma unroll
        for (int kk = 0; kk < 32; kk += 16) {
            wmma::fragment<wmma::matrix_a,16,16,16,__nv_bfloat16,wmma::row_major> af[2];
            wmma::fragment<wmma::matrix_b,16,16,16,__nv_bfloat16,wmma::col_major> bf[4];
            #pragma unroll
            for (int im = 0; im < 2; im++)
                wmma::load_matrix_sync(af[im], &sm.ab[st][0][wm*32 + im*16][kk], LDH);
            #pragma unroll
            for (int in = 0; in < 4; in++)
                wmma::load_matrix_sync(bf[in], &sm.ab[st][1][wn*64 + in*16][kk], LDH);
            #pragma unroll
            for (int im = 0; im < 2; im++)
                #pragma unroll
                for (int in = 0; in < 4; in++)
                    wmma::mma_sync(acc[im][in], af[im], bf[in], acc[im][in]);
        }
        __syncthreads();
    }

    // epilogue (smem reuse is safe: unconditional __syncthreads above)
    #pragma unroll
    for (int im = 0; im < 2; im++)
        #pragma unroll
        for (int in = 0; in < 4; in++) {
            wmma::store_matrix_sync(&sm.patch[warp][0][0], acc[im][in], 24, wmma::mem_row_major);
            __syncwarp();
            const int row0 = bm + wm*32 + im*16;
            const int col0 = bn + wn*64 + in*16;
            #pragma unroll
            for (int e = 0; e < 8; e++) {
                int idx = lane*8 + e;
                int r = idx >> 4, c = idx & 15;
                float v = sm.patch[warp][r][c] + __ldg(&bias[col0 + c]);
                if (EPI == 1) { v = v > 0.f ? v : 0.f; v = v*v; }
                if (OBF) Cb[(size_t)(row0 + r)*N + col0 + c] = __float2bfloat16(v);
                else     C [(size_t)(row0 + r)*N + col0 + c] = v;
            }
            __syncwarp();
        }
}

// ---------------- persistent GRU scan ----------------
__global__ __launch_bounds__(256, 1) void gru_kernel(
    const float* __restrict__ xp, const float* __restrict__ w_hh,
    const float* __restrict__ b_hh, float* __restrict__ states)
{
    const int warp = threadIdx.x >> 5;
    const int lane = threadIdx.x & 31;
    const int j = blockIdx.x * 8 + warp;

    float Wr[32], Wz[32], Wn[32];
    #pragma unroll
    for (int i = 0; i < 32; i++) {
        int c = lane + 32*i;
        Wr[i] = w_hh[(size_t)j*HDIM + c];
        Wz[i] = w_hh[(size_t)(HDIM + j)*HDIM + c];
        Wn[i] = w_hh[(size_t)(2*HDIM + j)*HDIM + c];
    }
    const float bhr = b_hh[j], bhz = b_hh[HDIM + j], bhn = b_hh[2*HDIM + j];

    __shared__ float hs[BATCH][HDIM];

    for (int t = 0; t < LSEQ; t++) {
        for (int idx = threadIdx.x; idx < BATCH*HDIM; idx += 256)
            (&hs[0][0])[idx] = __ldcg(&g_h[idx]);
        __syncthreads();

        float ar0=0.f,az0=0.f,an0=0.f, ar1=0.f,az1=0.f,an1=0.f;
        #pragma unroll
        for (int i = 0; i < 32; i++) {
            int c = lane + 32*i;
            float h0 = hs[0][c], h1 = hs[1][c];
            ar0 += Wr[i]*h0; az0 += Wz[i]*h0; an0 += Wn[i]*h0;
            ar1 += Wr[i]*h1; az1 += Wz[i]*h1; an1 += Wn[i]*h1;
        }
        #pragma unroll
        for (int off = 16; off; off >>= 1) {
            ar0 += __shfl_xor_sync(0xffffffffu, ar0, off);
            az0 += __shfl_xor_sync(0xffffffffu, az0, off);
            an0 += __shfl_xor_sync(0xffffffffu, an0, off);
            ar1 += __shfl_xor_sync(0xffffffffu, ar1, off);
            az1 += __shfl_xor_sync(0xffffffffu, az1, off);
            an1 += __shfl_xor_sync(0xffffffffu, an1, off);
        }
        if (lane < BATCH) {
            float hr, hz, hn;
            if (lane == 0) { hr = ar0; hz = az0; hn = an0; }
            else           { hr = ar1; hz = az1; hn = an1; }
            hr += bhr; hz += bhz; hn += bhn;
            const float* xrow = xp + ((size_t)(lane*LSEQ + t))*(3*HDIM);
            float r = 1.f/(1.f + __expf(-(xrow[j]          + hr)));
            float z = 1.f/(1.f + __expf(-(xrow[HDIM + j]   + hz)));
            float n = tanhf(xrow[2*HDIM + j] + r*hn);
            float hprev = hs[lane][j];
            float hnew = (1.f - z)*n + z*hprev;
            g_h[lane*HDIM + j] = hnew;
            states[((size_t)(lane*LSEQ + t))*HDIM + j] = hnew;
            __threadfence();
        }
        __syncthreads();
        if (threadIdx.x == 0) {
            atomicAdd(&g_bar, 1u);
            unsigned target = (unsigned)GRU_BLOCKS * (unsigned)(t + 1);
            while (*((volatile unsigned*)&g_bar) < target) { }
            __threadfence();
        }
        __syncthreads();
    }
}

// ---------------- gate ----------------
__global__ __launch_bounds__(256) void gate_kernel(
    const float* __restrict__ states, const float* __restrict__ wg,
    const float* __restrict__ bg, const float* __restrict__ ms)
{
    int r = blockIdx.x;
    float s = 0.f;
    for (int m = threadIdx.x; m < HDIM; m += 256)
        s += states[(size_t)r*HDIM + m] * wg[m];
    __shared__ float red[256];
    red[threadIdx.x] = s; __syncthreads();
    for (int o = 128; o; o >>= 1) { if (threadIdx.x < o) red[threadIdx.x] += red[threadIdx.x + o]; __syncthreads(); }
    if (threadIdx.x == 0) {
        float v = red[0] + bg[0];
        g_gate[r] = (1.f/(1.f + __expf(-v))) * ms[0];
    }
}

// ---------------- attention + softmax + scatter + final untied add ----------------
__global__ __launch_bounds__(256) void attn_scatter_kernel(
    const int* __restrict__ untied, float* __restrict__ out)
{
    const int r = blockIdx.x;
    const int b = r >> 11, l = r & (LSEQ - 1);
    const int tid = threadIdx.x;
    __shared__ float q_s[MDIM];
    __shared__ float sc[LSEQ];
    __shared__ float accp[PDIM];
    __shared__ float red[256];

    for (int p = tid; p < PDIM; p += 256) accp[p] = 0.f;

    if (l > 0) {
        for (int m = tid; m < MDIM; m += 256) q_s[m] = g_q[(size_t)r*MDIM + m];
        __syncthreads();
        const float* kb = g_k + (size_t)b*LSEQ*MDIM;
        for (int jj = tid; jj < l; jj += 256) {
            const float4* kr = reinterpret_cast<const float4*>(kb + (size_t)jj*MDIM);
            const float4* qr = reinterpret_cast<const float4*>(q_s);
            float s = 0.f;
            #pragma unroll 8
            for (int m = 0; m < MDIM/4; m++) {
                float4 kv = kr[m], qv = qr[m];
                s += kv.x*qv.x + kv.y*qv.y + kv.z*qv.z + kv.w*qv.w;
            }
            sc[jj] = s * 0.0625f;
        }
        __syncthreads();
        float mx = -3.4e38f;
        for (int jj = tid; jj < l; jj += 256) mx = fmaxf(mx, sc[jj]);
        red[tid] = mx; __syncthreads();
        for (int o = 128; o; o >>= 1) { if (tid < o) red[tid] = fmaxf(red[tid], red[tid + o]); __syncthreads(); }
        mx = red[0]; __syncthreads();
        float ls = 0.f;
        for (int jj = tid; jj < l; jj += 256) { float e = __expf(sc[jj] - mx); sc[jj] = e; ls += e; }
        red[tid] = ls; __syncthreads();
        for (int o = 128; o; o >>= 1) { if (tid < o) red[tid] += red[tid + o]; __syncthreads(); }
        float coef = g_gate[r] / red[0];
        const int* sl = g_slots + b*LSEQ;
        for (int jj = tid; jj < l; jj += 256) {
            int s = sl[jj];
            if (s >= 0) atomicAdd(&accp[s], sc[jj]*coef);
        }
    }
    __syncthreads();
    const float* pl = g_plin + (size_t)r*PDIM;
    float* orow = out + (size_t)r*VOCAB;
    for (int p = tid; p < PDIM; p += 256) {
        int col = untied[p];
        orow[col] += accp[p] + pl[p];
    }
}

// ---------------- launch ----------------
extern "C" void kernel_launch(void* const* d_in, const int* in_sizes, int n_in,
                              void* d_out, int out_size)
{
    const int*   ids     = (const int*)  d_in[0];
    const int*   untied  = (const int*)  d_in[1];
    const float* emb     = (const float*)d_in[2];
    const float* w_ih    = (const float*)d_in[3];
    const float* w_hh    = (const float*)d_in[4];
    const float* b_ih    = (const float*)d_in[5];
    const float* b_hh    = (const float*)d_in[6];
    const float* wq      = (const float*)d_in[7];
    const float* bq      = (const float*)d_in[8];
    const float* wk      = (const float*)d_in[9];
    const float* bk      = (const float*)d_in[10];
    const float* wg      = (const float*)d_in[11];
    const float* bg      = (const float*)d_in[12];
    const float* w_fc    = (const float*)d_in[13];
    const float* b_fc    = (const float*)d_in[14];
    const float* w_proj  = (const float*)d_in[15];
    const float* b_proj  = (const float*)d_in[16];
    const float* obias   = (const float*)d_in[17];
    const float* w_part  = (const float*)d_in[18];
    const float* b_part  = (const float*)d_in[19];
    const float* mscale  = (const float*)d_in[20];
    float* out = (float*)d_out;

    float *pxp, *pstates, *pq, *pk, *pplin;
    __nv_bfloat16 *px_bf, *pemb_bf, *pst_bf, *phead_bf, *pfeat_bf;
    __nv_bfloat16 *pwih, *pwfc, *pwproj, *pwq, *pwk, *pwpart;
    cudaGetSymbolAddress((void**)&pxp,     g_xp);
    cudaGetSymbolAddress((void**)&pstates, g_states);
    cudaGetSymbolAddress((void**)&pq,      g_q);
    cudaGetSymbolAddress((void**)&pk,      g_k);
    cudaGetSymbolAddress((void**)&pplin,   g_plin);
    cudaGetSymbolAddress((void**)&px_bf,   g_x_bf);
    cudaGetSymbolAddress((void**)&pemb_bf, g_emb_bf);
    cudaGetSymbolAddress((void**)&pst_bf,  g_states_bf);
    cudaGetSymbolAddress((void**)&phead_bf,g_head_bf);
    cudaGetSymbolAddress((void**)&pfeat_bf,g_feat_bf);
    cudaGetSymbolAddress((void**)&pwih,    g_wih_bf);
    cudaGetSymbolAddress((void**)&pwfc,    g_wfc_bf);
    cudaGetSymbolAddress((void**)&pwproj,  g_wproj_bf);
    cudaGetSymbolAddress((void**)&pwq,     g_wq_bf);
    cudaGetSymbolAddress((void**)&pwk,     g_wk_bf);
    cudaGetSymbolAddress((void**)&pwpart,  g_wpart_bf);

    init_a_kernel<<<(VOCAB + 255)/256, 256>>>();
    init_b_kernel<<<(PDIM + 255)/256, 256>>>(untied);
    init_c_kernel<<<(ROWS + 255)/256, 256>>>(ids);

    // fp32 -> bf16 conversions (counts in float4 units)
    auto conv = [](const float* s, __nv_bfloat16* d, size_t n) {
        int n4 = (int)(n >> 2);
        f2bf_kernel<<<(n4 + 255)/256, 256>>>(s, d, n4);
    };
    conv(emb,    pemb_bf, (size_t)VOCAB*EDIM);
    conv(w_ih,   pwih,    (size_t)3*HDIM*EDIM);
    conv(w_fc,   pwfc,    (size_t)4*EDIM*HDIM);
    conv(w_proj, pwproj,  (size_t)EDIM*4*EDIM);
    conv(wq,     pwq,     (size_t)MDIM*HDIM);
    conv(wk,     pwk,     (size_t)MDIM*HDIM);
    conv(w_part, pwpart,  (size_t)PDIM*EDIM);
    gather_x_bf_kernel<<<ROWS, 128>>>(ids, emb);

    // xp = x @ w_ih^T + b_ih (fp32 out)   [4096, 3072]
    hgemm_tn<0,0><<<dim3(3*HDIM/128, ROWS/128), 256>>>(px_bf, pwih, b_ih, pxp, nullptr, ROWS, 3*HDIM, EDIM);

    // sequential GRU scan -> states [4096, 1024]
    gru_kernel<<<GRU_BLOCKS, 256>>>(pxp, w_hh, b_hh, pstates);
    conv(pstates, pst_bf, (size_t)ROWS*HDIM);

    // head = relu(states @ w_fc^T + b_fc)^2 (bf16 out) [4096, 2048]
    hgemm_tn<1,1><<<dim3(4*EDIM/128, ROWS/128), 256>>>(pst_bf, pwfc, b_fc, nullptr, phead_bf, ROWS, 4*EDIM, HDIM);
    // base_feat = head @ w_proj^T + b_proj (bf16 out)  [4096, 512]
    hgemm_tn<0,1><<<dim3(EDIM/128, ROWS/128), 256>>>(phead_bf, pwproj, b_proj, nullptr, pfeat_bf, ROWS, EDIM, 4*EDIM);
    // q / k (fp32 out)                                  [4096, 256]
    hgemm_tn<0,0><<<dim3(MDIM/128, ROWS/128), 256>>>(pst_bf, pwq, bq, pq, nullptr, ROWS, MDIM, HDIM);
    hgemm_tn<0,0><<<dim3(MDIM/128, ROWS/128), 256>>>(pst_bf, pwk, bk, pk, nullptr, ROWS, MDIM, HDIM);
    gate_kernel<<<ROWS, 256>>>(pstates, wg, bg, mscale);

    // base_logits = base_feat @ emb^T + output_bias -> d_out [4096, 32000]
    hgemm_tn<0,0><<<dim3(VOCAB/128, ROWS/128), 256>>>(pfeat_bf, pemb_bf, obias, out, nullptr, ROWS, VOCAB, EDIM);
    // part_lin = base_feat @ w_partial^T + b_partial [4096, 4096]
    hgemm_tn<0,0><<<dim3(PDIM/128, ROWS/128), 256>>>(pfeat_bf, pwpart, b_part, pplin, nullptr, ROWS, PDIM, EDIM);

    // attention softmax + gated scatter + untied column add into d_out
    attn_scatter_kernel<<<ROWS, 256>>>(untied, out);
}

// round 7
// speedup vs baseline: 1.4719x; 1.1041x over previous
#include <cuda_runtime.h>
#include <cuda_bf16.h>
#include <math.h>
#include <stdint.h>

#define BATCH 2
#define LSEQ  2048
#define VOCAB 32000
#define EDIM  512
#define HDIM  1024
#define MDIM  256
#define PDIM  4096
#define ROWS  (BATCH*LSEQ)   /* 4096 */
#define GRU_BLOCKS 128

// ---------------- scratch (__device__ globals: allocation-free) ----------------
__device__ float g_xp[(size_t)ROWS*3*HDIM];
__device__ float g_states[(size_t)ROWS*HDIM];
__device__ float g_q[ROWS*MDIM];
__device__ float g_k[ROWS*MDIM];
__device__ float g_gate[ROWS];
__device__ float g_plin[(size_t)ROWS*PDIM];
__device__ float g_h[BATCH*HDIM];
__device__ int   g_t2p[VOCAB];
__device__ int   g_slots[ROWS];
__device__ unsigned g_bar;

// bf16 copies for tensor-core GEMMs
__device__ __nv_bfloat16 g_x_bf[ROWS*EDIM];
__device__ __nv_bfloat16 g_emb_bf[(size_t)VOCAB*EDIM];
__device__ __nv_bfloat16 g_states_bf[(size_t)ROWS*HDIM];
__device__ __nv_bfloat16 g_head_bf[(size_t)ROWS*4*EDIM];
__device__ __nv_bfloat16 g_feat_bf[ROWS*EDIM];
__device__ __nv_bfloat16 g_wih_bf[3*HDIM*EDIM];
__device__ __nv_bfloat16 g_wfc_bf[4*EDIM*HDIM];
__device__ __nv_bfloat16 g_wproj_bf[EDIM*4*EDIM];
__device__ __nv_bfloat16 g_wq_bf[MDIM*HDIM];
__device__ __nv_bfloat16 g_wk_bf[MDIM*HDIM];
__device__ __nv_bfloat16 g_wpart_bf[PDIM*EDIM];

// ---------------- init / convert kernels ----------------
__global__ void init_a_kernel() {
    int i = blockIdx.x*256 + threadIdx.x;
    if (i < VOCAB) g_t2p[i] = -1;
    if (i < BATCH*HDIM) g_h[i] = 0.f;
    if (i == 0) g_bar = 0u;
}
__global__ void init_b_kernel(const int* __restrict__ untied) {
    int i = blockIdx.x*256 + threadIdx.x;
    if (i < PDIM) g_t2p[untied[i]] = i;
}
__global__ void init_c_kernel(const int* __restrict__ ids) {
    int i = blockIdx.x*256 + threadIdx.x;
    if (i < ROWS) g_slots[i] = g_t2p[ids[i]];
}
__global__ void f2bf_kernel(const float* __restrict__ s, __nv_bfloat16* __restrict__ d, int n4) {
    int i = blockIdx.x*256 + threadIdx.x;
    if (i < n4) {
        float4 v = reinterpret_cast<const float4*>(s)[i];
        __nv_bfloat162 lo = __floats2bfloat162_rn(v.x, v.y);
        __nv_bfloat162 hi = __floats2bfloat162_rn(v.z, v.w);
        uint2 o;
        o.x = *reinterpret_cast<unsigned int*>(&lo);
        o.y = *reinterpret_cast<unsigned int*>(&hi);
        reinterpret_cast<uint2*>(d)[i] = o;
    }
}
__global__ void gather_x_bf_kernel(const int* __restrict__ ids, const float* __restrict__ emb) {
    int r = blockIdx.x;
    int tok = ids[r];
    const float4* src = reinterpret_cast<const float4*>(emb + (size_t)tok*EDIM);
    uint2* dst = reinterpret_cast<uint2*>(g_x_bf + (size_t)r*EDIM);
    for (int i = threadIdx.x; i < EDIM/4; i += 128) {
        float4 v = src[i];
        __nv_bfloat162 lo = __floats2bfloat162_rn(v.x, v.y);
        __nv_bfloat162 hi = __floats2bfloat162_rn(v.z, v.w);
        uint2 o;
        o.x = *reinterpret_cast<unsigned int*>(&lo);
        o.y = *reinterpret_cast<unsigned int*>(&hi);
        dst[i] = o;
    }
}

// ================= mma.sync bf16 GEMM =================
// C[M,N] = A[M,K] * B[N,K]^T + bias; 128x128 CTA tile, BK=64, 2-stage cp.async,
// 8 warps x (32x64) warp tile, ldmatrix + mma.m16n8k16, swizzled smem.
// NOTE: B is K-major ([n][k], k contiguous) -> B fragment loads use PLAIN
// ldmatrix (same as A). .trans would give a transposed (wrong) fragment.

__device__ __forceinline__ unsigned smem_u32(const void* p) {
    return (unsigned)__cvta_generic_to_shared(p);
}
__device__ __forceinline__ void cp16(unsigned dst, const void* src) {
    asm volatile("cp.async.cg.shared.global [%0], [%1], 16;" :: "r"(dst), "l"(src) : "memory");
}
__device__ __forceinline__ void ldsm4(unsigned addr, unsigned &r0, unsigned &r1, unsigned &r2, unsigned &r3) {
    asm volatile("ldmatrix.sync.aligned.m8n8.x4.shared.b16 {%0,%1,%2,%3}, [%4];"
        : "=r"(r0), "=r"(r1), "=r"(r2), "=r"(r3) : "r"(addr));
}
__device__ __forceinline__ void mma16816(float* c, unsigned a0, unsigned a1, unsigned a2, unsigned a3,
                                         unsigned b0, unsigned b1) {
    asm volatile("mma.sync.aligned.m16n8k16.row.col.f32.bf16.bf16.f32 "
        "{%0,%1,%2,%3}, {%4,%5,%6,%7}, {%8,%9}, {%0,%1,%2,%3};"
        : "+f"(c[0]), "+f"(c[1]), "+f"(c[2]), "+f"(c[3])
        : "r"(a0), "r"(a1), "r"(a2), "r"(a3), "r"(b0), "r"(b1));
}

#define TCS_STAGE 32768
#define TCS_DYN   (2*TCS_STAGE + 1024)

template<int EPI, int OBF>
__global__ __launch_bounds__(256, 2)
void mgemm(const __nv_bfloat16* __restrict__ A, const __nv_bfloat16* __restrict__ B,
           const float* __restrict__ bias, float* __restrict__ C,
           __nv_bfloat16* __restrict__ Cb, int M, int N, int K)
{
    extern __shared__ char smx[];
    const unsigned sdyn  = smem_u32(smx);
    const unsigned sbase = (sdyn + 1023u) & ~1023u;
    char* dynp = smx + (sbase - sdyn);

    const int tid = threadIdx.x, warp = tid >> 5, lane = tid & 31;
    const int wm = warp & 3, wn = warp >> 2;
    const int bm = blockIdx.y * 128, bn = blockIdx.x * 128;

    const __nv_bfloat16* Abase = A + (size_t)bm * K;
    const __nv_bfloat16* Bbase = B + (size_t)bn * K;

    float acc[2][8][4];
    #pragma unroll
    for (int i = 0; i < 2; i++)
        #pragma unroll
        for (int j = 0; j < 8; j++)
            #pragma unroll
            for (int e = 0; e < 4; e++) acc[i][j][e] = 0.f;

    // per-lane ldmatrix addressing constants
    const int r_local = ((lane >> 3) & 1) * 8 + (lane & 7);
    unsigned koff[4];
    {
        unsigned kh = ((unsigned)(lane >> 4)) << 4;      // khalf*16
        unsigned xm = ((unsigned)(lane & 7)) << 4;       // swizzle xor (== row&7 per lane)
        #pragma unroll
        for (int ks = 0; ks < 4; ks++) koff[ks] = (((unsigned)ks << 5) | kh) ^ xm;
    }
    unsigned aoff[2], boff[4];
    #pragma unroll
    for (int im = 0; im < 2; im++) aoff[im] = (unsigned)((wm*32 + im*16 + r_local) * 128);
    #pragma unroll
    for (int jn = 0; jn < 4; jn++) boff[jn] = (unsigned)((wn*64 + jn*16 + r_local) * 128);

    auto load_stage = [&](int s, int k0) {
        unsigned a_s = sbase + (unsigned)s * TCS_STAGE;
        unsigned b_s = a_s + 16384u;
        #pragma unroll
        for (int j = 0; j < 4; j++) {
            int id = tid + (j << 8);            // 0..1023
            int r = id >> 3, c16 = id & 7;
            unsigned so = (unsigned)(r * 128) + ((((unsigned)c16) << 4) ^ (((unsigned)(r & 7)) << 4));
            cp16(a_s + so, Abase + (size_t)r * K + k0 + c16 * 8);
            cp16(b_s + so, Bbase + (size_t)r * K + k0 + c16 * 8);
        }
        asm volatile("cp.async.commit_group;" ::: "memory");
    };

    const int NC = K >> 6;
    load_stage(0, 0);
    for (int c = 0; c < NC; c++) {
        const int s = c & 1;
        if (c + 1 < NC) {
            load_stage(s ^ 1, (c + 1) << 6);
            asm volatile("cp.async.wait_group 1;" ::: "memory");
        } else {
            asm volatile("cp.async.wait_group 0;" ::: "memory");
        }
        __syncthreads();
        const unsigned a_s = sbase + (unsigned)s * TCS_STAGE;
        const unsigned b_s = a_s + 16384u;
        #pragma unroll
        for (int ks = 0; ks < 4; ks++) {
            unsigned af[2][4];
            #pragma unroll
            for (int im = 0; im < 2; im++)
                ldsm4(a_s + aoff[im] + koff[ks], af[im][0], af[im][1], af[im][2], af[im][3]);
            #pragma unroll
            for (int jn = 0; jn < 4; jn++) {
                unsigned b0, b1, b2, b3;
                ldsm4(b_s + boff[jn] + koff[ks], b0, b1, b2, b3);   // plain ldmatrix (fix)
                #pragma unroll
                for (int im = 0; im < 2; im++) {
                    mma16816(acc[im][jn*2 + 0], af[im][0], af[im][1], af[im][2], af[im][3], b0, b2);
                    mma16816(acc[im][jn*2 + 1], af[im][0], af[im][1], af[im][2], af[im][3], b1, b3);
                }
            }
        }
        __syncthreads();
    }

    // epilogue: per-warp smem patch (reuses stage smem; all warps past final barrier)
    float* patch = reinterpret_cast<float*>(dynp) + warp * (32 * 36);
    const int row0 = bm + wm * 32;
    const int colw = bn + wn * 64;
    #pragma unroll
    for (int hf = 0; hf < 2; hf++) {
        #pragma unroll
        for (int im = 0; im < 2; im++)
            #pragma unroll
            for (int t4 = 0; t4 < 4; t4++) {
                const int t = hf * 4 + t4;
                const int r = im * 16 + (lane >> 2);
                const int cl = t4 * 8 + (lane & 3) * 2;
                const int cg = colw + hf * 32 + cl;
                float bz0 = __ldg(&bias[cg]), bz1 = __ldg(&bias[cg + 1]);
                float v0 = acc[im][t][0] + bz0;
                float v1 = acc[im][t][1] + bz1;
                float v2 = acc[im][t][2] + bz0;
                float v3 = acc[im][t][3] + bz1;
                if (EPI == 1) {
                    v0 = v0 > 0.f ? v0 * v0 : 0.f;
                    v1 = v1 > 0.f ? v1 * v1 : 0.f;
                    v2 = v2 > 0.f ? v2 * v2 : 0.f;
                    v3 = v3 > 0.f ? v3 * v3 : 0.f;
                }
                patch[r * 36 + cl]       = v0;
                patch[r * 36 + cl + 1]   = v1;
                patch[(r + 8) * 36 + cl]     = v2;
                patch[(r + 8) * 36 + cl + 1] = v3;
            }
        __syncwarp();
        #pragma unroll
        for (int it = 0; it < 8; it++) {
            int sIdx = lane + (it << 5);
            int rr = sIdx >> 3, q = sIdx & 7;
            float4 v = *reinterpret_cast<float4*>(&patch[rr * 36 + q * 4]);
            size_t g = (size_t)(row0 + rr) * N + colw + hf * 32 + q * 4;
            if (OBF) {
                __nv_bfloat162 lo = __floats2bfloat162_rn(v.x, v.y);
                __nv_bfloat162 hi = __floats2bfloat162_rn(v.z, v.w);
                uint2 o;
                o.x = *reinterpret_cast<unsigned int*>(&lo);
                o.y = *reinterpret_cast<unsigned int*>(&hi);
                *reinterpret_cast<uint2*>(&Cb[g]) = o;
            } else {
                *reinterpret_cast<float4*>(&C[g]) = v;
            }
        }
        __syncwarp();
    }
}

// ---------------- persistent GRU scan ----------------
__global__ __launch_bounds__(256, 1) void gru_kernel(
    const float* __restrict__ xp, const float* __restrict__ w_hh,
    const float* __restrict__ b_hh, float* __restrict__ states)
{
    const int warp = threadIdx.x >> 5;
    const int lane = threadIdx.x & 31;
    const int j = blockIdx.x * 8 + warp;

    float Wr[32], Wz[32], Wn[32];
    #pragma unroll
    for (int i = 0; i < 32; i++) {
        int c = lane + 32*i;
        Wr[i] = w_hh[(size_t)j*HDIM + c];
        Wz[i] = w_hh[(size_t)(HDIM + j)*HDIM + c];
        Wn[i] = w_hh[(size_t)(2*HDIM + j)*HDIM + c];
    }
    const float bhr = b_hh[j], bhz = b_hh[HDIM + j], bhn = b_hh[2*HDIM + j];

    __shared__ float hs[BATCH][HDIM];

    for (int t = 0; t < LSEQ; t++) {
        for (int idx = threadIdx.x; idx < BATCH*HDIM; idx += 256)
            (&hs[0][0])[idx] = __ldcg(&g_h[idx]);
        __syncthreads();

        float ar0=0.f,az0=0.f,an0=0.f, ar1=0.f,az1=0.f,an1=0.f;
        #pragma unroll
        for (int i = 0; i < 32; i++) {
            int c = lane + 32*i;
            float h0 = hs[0][c], h1 = hs[1][c];
            ar0 += Wr[i]*h0; az0 += Wz[i]*h0; an0 += Wn[i]*h0;
            ar1 += Wr[i]*h1; az1 += Wz[i]*h1; an1 += Wn[i]*h1;
        }
        #pragma unroll
        for (int off = 16; off; off >>= 1) {
            ar0 += __shfl_xor_sync(0xffffffffu, ar0, off);
            az0 += __shfl_xor_sync(0xffffffffu, az0, off);
            an0 += __shfl_xor_sync(0xffffffffu, an0, off);
            ar1 += __shfl_xor_sync(0xffffffffu, ar1, off);
            az1 += __shfl_xor_sync(0xffffffffu, az1, off);
            an1 += __shfl_xor_sync(0xffffffffu, an1, off);
        }
        if (lane < BATCH) {
            float hr, hz, hn;
            if (lane == 0) { hr = ar0; hz = az0; hn = an0; }
            else           { hr = ar1; hz = az1; hn = an1; }
            hr += bhr; hz += bhz; hn += bhn;
            const float* xrow = xp + ((size_t)(lane*LSEQ + t))*(3*HDIM);
            float r = 1.f/(1.f + __expf(-(xrow[j]          + hr)));
            float z = 1.f/(1.f + __expf(-(xrow[HDIM + j]   + hz)));
            float n = tanhf(xrow[2*HDIM + j] + r*hn);
            float hprev = hs[lane][j];
            float hnew = (1.f - z)*n + z*hprev;
            g_h[lane*HDIM + j] = hnew;
            states[((size_t)(lane*LSEQ + t))*HDIM + j] = hnew;
            __threadfence();
        }
        __syncthreads();
        if (threadIdx.x == 0) {
            atomicAdd(&g_bar, 1u);
            unsigned target = (unsigned)GRU_BLOCKS * (unsigned)(t + 1);
            while (*((volatile unsigned*)&g_bar) < target) { }
            __threadfence();
        }
        __syncthreads();
    }
}

// ---------------- gate ----------------
__global__ __launch_bounds__(256) void gate_kernel(
    const float* __restrict__ states, const float* __restrict__ wg,
    const float* __restrict__ bg, const float* __restrict__ ms)
{
    int r = blockIdx.x;
    float s = 0.f;
    for (int m = threadIdx.x; m < HDIM; m += 256)
        s += states[(size_t)r*HDIM + m] * wg[m];
    __shared__ float red[256];
    red[threadIdx.x] = s; __syncthreads();
    for (int o = 128; o; o >>= 1) { if (threadIdx.x < o) red[threadIdx.x] += red[threadIdx.x + o]; __syncthreads(); }
    if (threadIdx.x == 0) {
        float v = red[0] + bg[0];
        g_gate[r] = (1.f/(1.f + __expf(-v))) * ms[0];
    }
}

// ---------------- attention + softmax + scatter + final untied add ----------------
__global__ __launch_bounds__(256) void attn_scatter_kernel(
    const int* __restrict__ untied, float* __restrict__ out)
{
    const int r = blockIdx.x;
    const int b = r >> 11, l = r & (LSEQ - 1);
    const int tid = threadIdx.x;
    __shared__ float q_s[MDIM];
    __shared__ float sc[LSEQ];
    __shared__ float accp[PDIM];
    __shared__ float red[256];

    for (int p = tid; p < PDIM; p += 256) accp[p] = 0.f;

    if (l > 0) {
        for (int m = tid; m < MDIM; m += 256) q_s[m] = g_q[(size_t)r*MDIM + m];
        __syncthreads();
        const float* kb = g_k + (size_t)b*LSEQ*MDIM;
        for (int jj = tid; jj < l; jj += 256) {
            const float4* kr = reinterpret_cast<const float4*>(kb + (size_t)jj*MDIM);
            const float4* qr = reinterpret_cast<const float4*>(q_s);
            float s = 0.f;
            #pragma unroll 8
            for (int m = 0; m < MDIM/4; m++) {
                float4 kv = kr[m], qv = qr[m];
                s += kv.x*qv.x + kv.y*qv.y + kv.z*qv.z + kv.w*qv.w;
            }
            sc[jj] = s * 0.0625f;
        }
        __syncthreads();
        float mx = -3.4e38f;
        for (int jj = tid; jj < l; jj += 256) mx = fmaxf(mx, sc[jj]);
        red[tid] = mx; __syncthreads();
        for (int o = 128; o; o >>= 1) { if (tid < o) red[tid] = fmaxf(red[tid], red[tid + o]); __syncthreads(); }
        mx = red[0]; __syncthreads();
        float ls = 0.f;
        for (int jj = tid; jj < l; jj += 256) { float e = __expf(sc[jj] - mx); sc[jj] = e; ls += e; }
        red[tid] = ls; __syncthreads();
        for (int o = 128; o; o >>= 1) { if (tid < o) red[tid] += red[tid + o]; __syncthreads(); }
        float coef = g_gate[r] / red[0];
        const int* sl = g_slots + b*LSEQ;
        for (int jj = tid; jj < l; jj += 256) {
            int s = sl[jj];
            if (s >= 0) atomicAdd(&accp[s], sc[jj]*coef);
        }
    }
    __syncthreads();
    const float* pl = g_plin + (size_t)r*PDIM;
    float* orow = out + (size_t)r*VOCAB;
    for (int p = tid; p < PDIM; p += 256) {
        int col = untied[p];
        orow[col] += accp[p] + pl[p];
    }
}

// ---------------- launch ----------------
extern "C" void kernel_launch(void* const* d_in, const int* in_sizes, int n_in,
                              void* d_out, int out_size)
{
    const int*   ids     = (const int*)  d_in[0];
    const int*   untied  = (const int*)  d_in[1];
    const float* emb     = (const float*)d_in[2];
    const float* w_ih    = (const float*)d_in[3];
    const float* w_hh    = (const float*)d_in[4];
    const float* b_ih    = (const float*)d_in[5];
    const float* b_hh    = (const float*)d_in[6];
    const float* wq      = (const float*)d_in[7];
    const float* bq      = (const float*)d_in[8];
    const float* wk      = (const float*)d_in[9];
    const float* bk      = (const float*)d_in[10];
    const float* wg      = (const float*)d_in[11];
    const float* bg      = (const float*)d_in[12];
    const float* w_fc    = (const float*)d_in[13];
    const float* b_fc    = (const float*)d_in[14];
    const float* w_proj  = (const float*)d_in[15];
    const float* b_proj  = (const float*)d_in[16];
    const float* obias   = (const float*)d_in[17];
    const float* w_part  = (const float*)d_in[18];
    const float* b_part  = (const float*)d_in[19];
    const float* mscale  = (const float*)d_in[20];
    float* out = (float*)d_out;

    float *pxp, *pstates, *pq, *pk, *pplin;
    __nv_bfloat16 *px_bf, *pemb_bf, *pst_bf, *phead_bf, *pfeat_bf;
    __nv_bfloat16 *pwih, *pwfc, *pwproj, *pwq, *pwk, *pwpart;
    cudaGetSymbolAddress((void**)&pxp,     g_xp);
    cudaGetSymbolAddress((void**)&pstates, g_states);
    cudaGetSymbolAddress((void**)&pq,      g_q);
    cudaGetSymbolAddress((void**)&pk,      g_k);
    cudaGetSymbolAddress((void**)&pplin,   g_plin);
    cudaGetSymbolAddress((void**)&px_bf,   g_x_bf);
    cudaGetSymbolAddress((void**)&pemb_bf, g_emb_bf);
    cudaGetSymbolAddress((void**)&pst_bf,  g_states_bf);
    cudaGetSymbolAddress((void**)&phead_bf,g_head_bf);
    cudaGetSymbolAddress((void**)&pfeat_bf,g_feat_bf);
    cudaGetSymbolAddress((void**)&pwih,    g_wih_bf);
    cudaGetSymbolAddress((void**)&pwfc,    g_wfc_bf);
    cudaGetSymbolAddress((void**)&pwproj,  g_wproj_bf);
    cudaGetSymbolAddress((void**)&pwq,     g_wq_bf);
    cudaGetSymbolAddress((void**)&pwk,     g_wk_bf);
    cudaGetSymbolAddress((void**)&pwpart,  g_wpart_bf);

    cudaFuncSetAttribute(mgemm<0,0>, cudaFuncAttributeMaxDynamicSharedMemorySize, TCS_DYN);
    cudaFuncSetAttribute(mgemm<1,1>, cudaFuncAttributeMaxDynamicSharedMemorySize, TCS_DYN);
    cudaFuncSetAttribute(mgemm<0,1>, cudaFuncAttributeMaxDynamicSharedMemorySize, TCS_DYN);

    init_a_kernel<<<(VOCAB + 255)/256, 256>>>();
    init_b_kernel<<<(PDIM + 255)/256, 256>>>(untied);
    init_c_kernel<<<(ROWS + 255)/256, 256>>>(ids);

    auto conv = [](const float* s, __nv_bfloat16* d, size_t n) {
        int n4 = (int)(n >> 2);
        f2bf_kernel<<<(n4 + 255)/256, 256>>>(s, d, n4);
    };
    conv(emb,    pemb_bf, (size_t)VOCAB*EDIM);
    conv(w_ih,   pwih,    (size_t)3*HDIM*EDIM);
    conv(w_fc,   pwfc,    (size_t)4*EDIM*HDIM);
    conv(w_proj, pwproj,  (size_t)EDIM*4*EDIM);
    conv(wq,     pwq,     (size_t)MDIM*HDIM);
    conv(wk,     pwk,     (size_t)MDIM*HDIM);
    conv(w_part, pwpart,  (size_t)PDIM*EDIM);
    gather_x_bf_kernel<<<ROWS, 128>>>(ids, emb);

    // xp = x @ w_ih^T + b_ih (fp32 out)   [4096, 3072]
    mgemm<0,0><<<dim3(3*HDIM/128, ROWS/128), 256, TCS_DYN>>>(px_bf, pwih, b_ih, pxp, nullptr, ROWS, 3*HDIM, EDIM);

    // sequential GRU scan -> states [4096, 1024]
    gru_kernel<<<GRU_BLOCKS, 256>>>(pxp, w_hh, b_hh, pstates);
    conv(pstates, pst_bf, (size_t)ROWS*HDIM);

    // head = relu(states @ w_fc^T + b_fc)^2 (bf16 out) [4096, 2048]
    mgemm<1,1><<<dim3(4*EDIM/128, ROWS/128), 256, TCS_DYN>>>(pst_bf, pwfc, b_fc, nullptr, phead_bf, ROWS, 4*EDIM, HDIM);
    // base_feat = head @ w_proj^T + b_proj (bf16 out)  [4096, 512]
    mgemm<0,1><<<dim3(EDIM/128, ROWS/128), 256, TCS_DYN>>>(phead_bf, pwproj, b_proj, nullptr, pfeat_bf, ROWS, EDIM, 4*EDIM);
    // q / k (fp32 out)                                  [4096, 256]
    mgemm<0,0><<<dim3(MDIM/128, ROWS/128), 256, TCS_DYN>>>(pst_bf, pwq, bq, pq, nullptr, ROWS, MDIM, HDIM);
    mgemm<0,0><<<dim3(MDIM/128, ROWS/128), 256, TCS_DYN>>>(pst_bf, pwk, bk, pk, nullptr, ROWS, MDIM, HDIM);
    gate_kernel<<<ROWS, 256>>>(pstates, wg, bg, mscale);

    // base_logits = base_feat @ emb^T + output_bias -> d_out [4096, 32000]
    mgemm<0,0><<<dim3(VOCAB/128, ROWS/128), 256, TCS_DYN>>>(pfeat_bf, pemb_bf, obias, out, nullptr, ROWS, VOCAB, EDIM);
    // part_lin = base_feat @ w_partial^T + b_partial [4096, 4096]
    mgemm<0,0><<<dim3(PDIM/128, ROWS/128), 256, TCS_DYN>>>(pfeat_bf, pwpart, b_part, pplin, nullptr, ROWS, PDIM, EDIM);

    // attention softmax + gated scatter + untied column add into d_out
    attn_scatter_kernel<<<ROWS, 256>>>(untied, out);
}